// round 14
// baseline (speedup 1.0000x reference)
#include <cuda_runtime.h>
#include <cuda_fp16.h>
#include <stdint.h>

#define D_    1024
#define H_    768
#define HS_   1536
#define E_    8
#define TMAX  2048
#define AMAX  (TMAX*2)

#define KSZ   32
#define STR   40                      // smem row stride in fp16 elems (80B, conflict-free)
#define MATB  (128*STR*2)             // 10240 B per matrix tile
#define STAGEB (2*MATB)               // A, B -> 20480 B
#define NSTAGE 3
#define SMEM_BYTES (NSTAGE*STAGEB)    // 61440 B, triple buffered

// ---------------- routing scratch ----------------
__device__ int   g_counts[E_];
__device__ int   g_offs[E_ + 1];
__device__ int   g_cursor[E_];
__device__ int   g_top[AMAX];
__device__ float g_wgt[AMAX];
__device__ int   g_bucket[AMAX];
__device__ float g_bw[AMAX];

// ---------------- fp16 operand scratch ----------------
__device__ __align__(16) __half g_xq[TMAX * D_];
__device__ __align__(16) __half g_W1q[E_ * 2 * H_ * D_];
__device__ __align__(16) __half g_W2q[E_ * D_ * H_];
__device__ __align__(16) __half g_S1q[2 * HS_ * D_];
__device__ __align__(16) __half g_S2q[D_ * HS_];
__device__ __align__(16) __half g_aRq[AMAX * H_];
__device__ __align__(16) __half g_aSq[TMAX * HS_];

// ---------------- PTX helpers ----------------
__device__ __forceinline__ uint32_t cvta_s(const void* p) {
    return (uint32_t)__cvta_generic_to_shared(p);
}
#define CPA(dst, src) asm volatile("cp.async.cg.shared.global [%0], [%1], 16;\n" :: "r"(dst), "l"(src))
#define CPC() asm volatile("cp.async.commit_group;\n")
#define CPW2() asm volatile("cp.async.wait_group 2;\n")
#define CPW1() asm volatile("cp.async.wait_group 1;\n")
#define CPW0() asm volatile("cp.async.wait_group 0;\n")
#define LDM4(r0, r1, r2, r3, a) \
    asm volatile("ldmatrix.sync.aligned.m8n8.x4.shared.b16 {%0,%1,%2,%3}, [%4];" \
        : "=r"(r0), "=r"(r1), "=r"(r2), "=r"(r3) : "r"(a))
#define MMA(c, a, b) \
    asm volatile("mma.sync.aligned.m16n8k16.row.col.f32.f16.f16.f32 " \
        "{%0,%1,%2,%3},{%4,%5,%6,%7},{%8,%9},{%0,%1,%2,%3};" \
        : "+f"(c[0]), "+f"(c[1]), "+f"(c[2]), "+f"(c[3]) \
        : "r"(a[0]), "r"(a[1]), "r"(a[2]), "r"(a[3]), "r"(b[0]), "r"(b[1]))

// ---------------- fused conversion + counter zero + output zero ----------------
struct CvtArgs {
    const float* s[5];
    __half* h[5];
    float* outz;
    int bend[6];   // 5 cvt regions + 1 zero region (cumulative block bounds)
};

__global__ void k_cvt_all(CvtArgs a) {
    if (blockIdx.x == 0 && threadIdx.x < 2 * E_) {
        if (threadIdx.x < E_) g_counts[threadIdx.x] = 0;
        else                  g_cursor[threadIdx.x - E_] = 0;
    }
    int b = blockIdx.x;
    int i = 0;
    while (i < 5 && b >= a.bend[i]) i++;
    int lb = b - (i ? a.bend[i - 1] : 0);
    int idx = lb * 256 + threadIdx.x;          // index of 8-elem chunk

    if (i == 5) {                               // zero the output buffer
        float4 z = make_float4(0.f, 0.f, 0.f, 0.f);
        ((float4*)a.outz)[idx * 2] = z;
        ((float4*)a.outz)[idx * 2 + 1] = z;
        return;
    }

    const float4* src = (const float4*)a.s[i];
    float4 v0 = src[idx * 2];
    float4 v1 = src[idx * 2 + 1];
    float f[8] = {v0.x, v0.y, v0.z, v0.w, v1.x, v1.y, v1.z, v1.w};
    uint32_t hp[4];
#pragma unroll
    for (int p = 0; p < 4; p++) {
        __half h0 = __float2half_rn(f[p * 2]);
        __half h1 = __float2half_rn(f[p * 2 + 1]);
        hp[p] = (uint32_t)__half_as_ushort(h0) | ((uint32_t)__half_as_ushort(h1) << 16);
    }
    ((uint4*)a.h[i])[idx] = make_uint4(hp[0], hp[1], hp[2], hp[3]);
}

// ---------------- gate (fp32, proven) ----------------
__global__ void k_gate(const float* __restrict__ x, const float* __restrict__ gw, int T) {
    __shared__ float sg[E_ * D_];
    const float4* gw4 = (const float4*)gw;
    float4* sg4 = (float4*)sg;
    for (int i = threadIdx.x; i < E_ * D_ / 4; i += blockDim.x) sg4[i] = gw4[i];
    __syncthreads();

    int wid = threadIdx.x >> 5, lane = threadIdx.x & 31;
    int t = blockIdx.x * 8 + wid;
    if (t >= T) return;

    float acc[E_];
#pragma unroll
    for (int e = 0; e < E_; e++) acc[e] = 0.f;
    const float4* xr = (const float4*)(x + (size_t)t * D_);
    for (int i = lane; i < D_ / 4; i += 32) {
        float4 xv = xr[i];
#pragma unroll
        for (int e = 0; e < E_; e++) {
            float4 g = sg4[e * (D_ / 4) + i];
            acc[e] += xv.x * g.x + xv.y * g.y + xv.z * g.z + xv.w * g.w;
        }
    }
#pragma unroll
    for (int e = 0; e < E_; e++)
#pragma unroll
        for (int o = 16; o > 0; o >>= 1) acc[e] += __shfl_xor_sync(0xffffffffu, acc[e], o);

    if (lane == 0) {
        float m = acc[0];
#pragma unroll
        for (int e = 1; e < E_; e++) m = fmaxf(m, acc[e]);
        float p[E_]; float s = 0.f;
#pragma unroll
        for (int e = 0; e < E_; e++) { p[e] = __expf(acc[e] - m); s += p[e]; }
        float inv = 1.f / s;
#pragma unroll
        for (int e = 0; e < E_; e++) p[e] *= inv;
        int i0 = 0; float v0 = p[0];
#pragma unroll
        for (int e = 1; e < E_; e++) if (p[e] > v0) { v0 = p[e]; i0 = e; }
        int i1 = -1; float v1 = -1.f;
#pragma unroll
        for (int e = 0; e < E_; e++) if (e != i0 && p[e] > v1) { v1 = p[e]; i1 = e; }
        g_top[t * 2] = i0;  g_top[t * 2 + 1] = i1;
        g_wgt[t * 2] = v0;  g_wgt[t * 2 + 1] = v1;
        atomicAdd(&g_counts[i0], 1);
        atomicAdd(&g_counts[i1], 1);
    }
}

// ---------------- scatter + offsets (fused) ----------------
__global__ void k_scatter(int T) {
    int i = blockIdx.x * blockDim.x + threadIdx.x;
    if (blockIdx.x == 0 && threadIdx.x == 0) {
        int s = 0;
        for (int e = 0; e < E_; e++) { g_offs[e] = s; s += g_counts[e]; }
        g_offs[E_] = s;
    }
    if (i >= T * 2) return;
    int t = i >> 1;
    int e = g_top[i];
    int off = 0;
#pragma unroll
    for (int j = 0; j < E_; j++) off += (j < e) ? g_counts[j] : 0;
    int pos = atomicAdd(&g_cursor[e], 1);
    g_bucket[off + pos] = t;
    g_bw[off + pos] = g_wgt[i];
}

// ======================================================================
// fc1 merged (routed + shared): plain fp16 GEMM, 3-stage pipeline,
// 3 CTAs/SM. CTA: 128 rows x 64 features. SiLU fused; acts -> fp16.
// grid.y: [0,24) shared; [24,120) routed (e=(zy-24)/12).
// ======================================================================
__global__ __launch_bounds__(256, 3)
void k_fc1(const __half* __restrict__ xq, const __half* __restrict__ W1q,
           const __half* __restrict__ S1q, __half* __restrict__ aRq,
           __half* __restrict__ aSq, int T) {
    extern __shared__ __half sm[];
    __shared__ int toks[128];

    int zy = blockIdx.y;
    bool routed = zy >= 24;
    int e = routed ? (zy - 24) / 12 : 0;
    int ytile = routed ? (zy - 24) % 12 : zy;
    int hid = routed ? H_ : HS_;
    const __half* W = routed ? W1q + (size_t)e * 2 * H_ * D_ : S1q;
    __half* Oq = routed ? aRq : aSq;
    int rbase = routed ? g_offs[e] : 0;
    int mcount = routed ? (g_offs[e + 1] - rbase) : T;
    int m0 = blockIdx.x * 128;
    if (m0 >= mcount) return;
    int n0f = ytile * 64;
    int tid = threadIdx.x;

    if (tid < 128) {
        int r = m0 + tid; if (r > mcount - 1) r = mcount - 1;
        toks[tid] = routed ? g_bucket[rbase + r] : r;
    }
    __syncthreads();

    uint32_t sbase = cvta_s(sm);
    const int K = D_;
    const int nst = K / KSZ;

    auto load_stage = [&](int s) {
        uint32_t sb = sbase + (uint32_t)(s % NSTAGE) * STAGEB;
        int k0 = s * KSZ;
#pragma unroll
        for (int j = 0; j < 4; j++) {
            int c = tid + 256 * j;
            int mat = c >> 9;             // 0=A, 1=B
            int rc = c & 511;
            int row = rc >> 2;
            int ch = rc & 3;
            uint32_t dst = sb + (uint32_t)(mat * MATB + (row * STR + ch * 8) * 2);
            const __half* src;
            if (mat == 0) {
                src = xq + (size_t)toks[row] * K + k0 + ch * 8;
            } else {
                int f = n0f + (row >> 1);
                int srow = (row & 1) ? (hid + f) : f;
                src = W + (size_t)srow * K + k0 + ch * 8;
            }
            CPA(dst, src);
        }
        CPC();
    };

    int wid = tid >> 5, lane = tid & 31;
    int wm = wid >> 2, wn = wid & 3;

    float c[4][4][4];
#pragma unroll
    for (int a = 0; a < 4; a++)
#pragma unroll
        for (int b = 0; b < 4; b++)
#pragma unroll
            for (int d = 0; d < 4; d++) c[a][b][d] = 0.f;

    int arow = wm * 64 + (lane & 15);
    int acol0 = (lane >> 4) * 8;
    int g8 = lane >> 3;
    int brin = lane & 7;

    load_stage(0);
    load_stage(1);
    for (int s = 0; s < nst; s++) {
        if (s + 2 < nst)      { load_stage(s + 2); CPW2(); }
        else if (s + 1 < nst) { CPW1(); }
        else                  { CPW0(); }
        __syncthreads();
        uint32_t sb = sbase + (uint32_t)(s % NSTAGE) * STAGEB;
        uint32_t Ab = sb;
        uint32_t Bb = sb + MATB;
#pragma unroll
        for (int ks = 0; ks < 2; ks++) {
            uint32_t af[4][4], bf[4][2];
#pragma unroll
            for (int mi = 0; mi < 4; mi++) {
                uint32_t off = (uint32_t)((arow + mi * 16) * STR + ks * 16 + acol0) * 2;
                LDM4(af[mi][0], af[mi][1], af[mi][2], af[mi][3], Ab + off);
            }
#pragma unroll
            for (int j2 = 0; j2 < 2; j2++) {
                int nf = j2 * 2 + (g8 >> 1);
                uint32_t off = (uint32_t)((wn * 32 + nf * 8 + brin) * STR + ks * 16 + (g8 & 1) * 8) * 2;
                uint32_t r0, r1, r2, r3;
                LDM4(r0, r1, r2, r3, Bb + off);
                bf[j2 * 2][0] = r0; bf[j2 * 2][1] = r1; bf[j2 * 2 + 1][0] = r2; bf[j2 * 2 + 1][1] = r3;
            }
#pragma unroll
            for (int mi = 0; mi < 4; mi++)
#pragma unroll
                for (int nj = 0; nj < 4; nj++) MMA(c[mi][nj], af[mi], bf[nj]);
        }
        __syncthreads();
    }

    int rrem = mcount - m0;
#pragma unroll
    for (int mi = 0; mi < 4; mi++)
#pragma unroll
        for (int half = 0; half < 2; half++) {
            int row = wm * 64 + mi * 16 + (lane >> 2) + half * 8;
            if (row < rrem) {
                size_t rb = (size_t)(rbase + m0 + row) * hid;
#pragma unroll
                for (int nj = 0; nj < 4; nj++) {
                    float y = c[mi][nj][half * 2 + 0];
                    float g = c[mi][nj][half * 2 + 1];
                    float a = y * g / (1.f + __expf(-g));
                    int f = n0f + wn * 16 + nj * 4 + (lane & 3);
                    Oq[rb + f] = __float2half_rn(a);
                }
            }
        }
}

// ======================================================================
// fc2 merged (shared z=0 first, routed z=1..8): fp16 GEMM tile 128x128,
// 3-stage pipeline, 3 CTAs/SM. Output pre-zeroed; both paths atomicAdd.
// ======================================================================
__global__ __launch_bounds__(256, 3)
void k_fc2(const __half* __restrict__ aRq, const __half* __restrict__ aSq,
           const __half* __restrict__ W2q, const __half* __restrict__ S2q,
           float* __restrict__ out, int T) {
    extern __shared__ __half sm[];
    __shared__ int   toks[128];
    __shared__ int   etok[128];
    __shared__ float ew[128];

    int z = blockIdx.z;
    bool routed = z >= 1;
    int e = routed ? z - 1 : 0;
    int K = routed ? H_ : HS_;
    const __half* A = routed ? aRq : aSq;
    const __half* W = routed ? W2q + (size_t)e * D_ * H_ : S2q;
    int rbase = routed ? g_offs[e] : 0;
    int mcount = routed ? (g_offs[e + 1] - rbase) : T;
    int m0 = blockIdx.x * 128;
    if (m0 >= mcount) return;
    int n0 = blockIdx.y * 128;
    int tid = threadIdx.x;

    if (tid < 128) {
        int r = m0 + tid; if (r > mcount - 1) r = mcount - 1;
        toks[tid] = rbase + r;
        if (routed) { etok[tid] = g_bucket[rbase + r]; ew[tid] = g_bw[rbase + r]; }
        else        { etok[tid] = r;                   ew[tid] = 1.f; }
    }
    __syncthreads();

    uint32_t sbase = cvta_s(sm);
    const int nst = K / KSZ;

    auto load_stage = [&](int s) {
        uint32_t sb = sbase + (uint32_t)(s % NSTAGE) * STAGEB;
        int k0 = s * KSZ;
#pragma unroll
        for (int j = 0; j < 4; j++) {
            int c = tid + 256 * j;
            int mat = c >> 9;             // 0=A, 1=B
            int rc = c & 511;
            int row = rc >> 2;
            int ch = rc & 3;
            uint32_t dst = sb + (uint32_t)(mat * MATB + (row * STR + ch * 8) * 2);
            const __half* src;
            if (mat == 0) {
                src = A + (size_t)toks[row] * K + k0 + ch * 8;
            } else {
                src = W + (size_t)(n0 + row) * K + k0 + ch * 8;
            }
            CPA(dst, src);
        }
        CPC();
    };

    int wid = tid >> 5, lane = tid & 31;
    int wm = wid >> 2, wn = wid & 3;

    float c[4][4][4];
#pragma unroll
    for (int a = 0; a < 4; a++)
#pragma unroll
        for (int b = 0; b < 4; b++)
#pragma unroll
            for (int d = 0; d < 4; d++) c[a][b][d] = 0.f;

    int arow = wm * 64 + (lane & 15);
    int acol0 = (lane >> 4) * 8;
    int g8 = lane >> 3;
    int brin = lane & 7;

    load_stage(0);
    load_stage(1);
    for (int s = 0; s < nst; s++) {
        if (s + 2 < nst)      { load_stage(s + 2); CPW2(); }
        else if (s + 1 < nst) { CPW1(); }
        else                  { CPW0(); }
        __syncthreads();
        uint32_t sb = sbase + (uint32_t)(s % NSTAGE) * STAGEB;
        uint32_t Ab = sb;
        uint32_t Bb = sb + MATB;
#pragma unroll
        for (int ks = 0; ks < 2; ks++) {
            uint32_t af[4][4], bf[4][2];
#pragma unroll
            for (int mi = 0; mi < 4; mi++) {
                uint32_t off = (uint32_t)((arow + mi * 16) * STR + ks * 16 + acol0) * 2;
                LDM4(af[mi][0], af[mi][1], af[mi][2], af[mi][3], Ab + off);
            }
#pragma unroll
            for (int j2 = 0; j2 < 2; j2++) {
                int nf = j2 * 2 + (g8 >> 1);
                uint32_t off = (uint32_t)((wn * 32 + nf * 8 + brin) * STR + ks * 16 + (g8 & 1) * 8) * 2;
                uint32_t r0, r1, r2, r3;
                LDM4(r0, r1, r2, r3, Bb + off);
                bf[j2 * 2][0] = r0; bf[j2 * 2][1] = r1; bf[j2 * 2 + 1][0] = r2; bf[j2 * 2 + 1][1] = r3;
            }
#pragma unroll
            for (int mi = 0; mi < 4; mi++)
#pragma unroll
                for (int nj = 0; nj < 4; nj++) MMA(c[mi][nj], af[mi], bf[nj]);
        }
        __syncthreads();
    }

    int rrem = mcount - m0;
#pragma unroll
    for (int mi = 0; mi < 4; mi++)
#pragma unroll
        for (int half = 0; half < 2; half++) {
            int row = wm * 64 + mi * 16 + (lane >> 2) + half * 8;
            if (row < rrem) {
                int t = etok[row]; float w = ew[row];
                float* base = out + (size_t)t * D_;
#pragma unroll
                for (int nj = 0; nj < 4; nj++) {
                    int col = n0 + wn * 32 + nj * 8 + (lane & 3) * 2;
                    atomicAdd(base + col,     w * c[mi][nj][half * 2 + 0]);
                    atomicAdd(base + col + 1, w * c[mi][nj][half * 2 + 1]);
                }
            }
        }
}

// ---------------- launcher ----------------
extern "C" void kernel_launch(void* const* d_in, const int* in_sizes, int n_in,
                              void* d_out, int out_size) {
    const float* x   = (const float*)d_in[0];
    const float* gw  = (const float*)d_in[1];
    const float* W1  = (const float*)d_in[2];
    const float* W2  = (const float*)d_in[3];
    const float* Ws1 = (const float*)d_in[4];
    const float* Ws2 = (const float*)d_in[5];
    float* out = (float*)d_out;

    int T = in_sizes[0] / D_;
    if (T > TMAX) T = TMAX;

    __half *xq, *W1q, *W2q, *S1q, *S2q, *aRq, *aSq;
    cudaGetSymbolAddress((void**)&xq,  g_xq);
    cudaGetSymbolAddress((void**)&W1q, g_W1q);
    cudaGetSymbolAddress((void**)&W2q, g_W2q);
    cudaGetSymbolAddress((void**)&S1q, g_S1q);
    cudaGetSymbolAddress((void**)&S2q, g_S2q);
    cudaGetSymbolAddress((void**)&aRq, g_aRq);
    cudaGetSymbolAddress((void**)&aSq, g_aSq);

    cudaFuncSetAttribute(k_fc1, cudaFuncAttributeMaxDynamicSharedMemorySize, SMEM_BYTES);
    cudaFuncSetAttribute(k_fc2, cudaFuncAttributeMaxDynamicSharedMemorySize, SMEM_BYTES);

    // fused conversion + counter zero + output zero (single launch)
    CvtArgs ca;
    ca.s[0] = x;   ca.h[0] = xq;
    ca.s[1] = W1;  ca.h[1] = W1q;
    ca.s[2] = W2;  ca.h[2] = W2q;
    ca.s[3] = Ws1; ca.h[3] = S1q;
    ca.s[4] = Ws2; ca.h[4] = S2q;
    ca.outz = out;
    int nb[6] = {
        (T * D_ / 8) / 256,
        (E_ * 2 * H_ * D_ / 8) / 256,
        (E_ * D_ * H_ / 8) / 256,
        (2 * HS_ * D_ / 8) / 256,
        (D_ * HS_ / 8) / 256,
        (T * D_ / 8) / 256            // output zeroing region
    };
    int cum = 0;
    for (int i = 0; i < 6; i++) { cum += nb[i]; ca.bend[i] = cum; }
    k_cvt_all<<<cum, 256>>>(ca);

    // routing: gate, then scatter (offsets fused into scatter)
    k_gate<<<(T + 7) / 8, 256>>>(x, gw, T);
    k_scatter<<<(T * 2 + 255) / 256, 256>>>(T);

    int mt = (T + 127) / 128;

    // fc1 merged: 24 shared tiles + 96 routed tiles in one launch
    k_fc1<<<dim3(mt, 120), 256, SMEM_BYTES>>>(xq, W1q, S1q, aRq, aSq, T);

    // fc2 merged: shared (z=0, scheduled first) + routed (z=1..8)
    k_fc2<<<dim3(mt, D_ / 128, 1 + E_), 256, SMEM_BYTES>>>(aRq, aSq, W2q, S2q, out, T);
}

// round 15
// speedup vs baseline: 1.8880x; 1.8880x over previous
#include <cuda_runtime.h>
#include <cuda_fp16.h>
#include <stdint.h>

#define D_    1024
#define H_    768
#define HS_   1536
#define E_    8
#define TMAX  2048
#define AMAX  (TMAX*2)

#define KSZ   64
#define STR   72                      // smem row stride in fp16 elems (144B; 8 rows -> 8 distinct 16B banks)
#define MATB  (128*STR*2)             // 18432 B per matrix tile (128 rows x 64 elems + pad)
#define STAGEB (2*MATB)               // A, B -> 36864 B
#define SMEM_BYTES (2*STAGEB)         // 73728 B, double buffered

// ---------------- routing scratch ----------------
__device__ int   g_counts[E_];
__device__ int   g_offs[E_ + 1];
__device__ int   g_cursor[E_];
__device__ int   g_top[AMAX];
__device__ float g_wgt[AMAX];
__device__ int   g_bucket[AMAX];
__device__ float g_bw[AMAX];

// ---------------- fp16 operand scratch ----------------
__device__ __align__(16) __half g_xq[TMAX * D_];
__device__ __align__(16) __half g_W1q[E_ * 2 * H_ * D_];
__device__ __align__(16) __half g_W2q[E_ * D_ * H_];
__device__ __align__(16) __half g_S1q[2 * HS_ * D_];
__device__ __align__(16) __half g_S2q[D_ * HS_];
__device__ __align__(16) __half g_aRq[AMAX * H_];
__device__ __align__(16) __half g_aSq[TMAX * HS_];

// ---------------- PTX helpers ----------------
__device__ __forceinline__ uint32_t cvta_s(const void* p) {
    return (uint32_t)__cvta_generic_to_shared(p);
}
#define CPA(dst, src) asm volatile("cp.async.cg.shared.global [%0], [%1], 16;\n" :: "r"(dst), "l"(src))
#define CPC() asm volatile("cp.async.commit_group;\n")
#define CPW1() asm volatile("cp.async.wait_group 1;\n")
#define CPW0() asm volatile("cp.async.wait_group 0;\n")
#define LDM4(r0, r1, r2, r3, a) \
    asm volatile("ldmatrix.sync.aligned.m8n8.x4.shared.b16 {%0,%1,%2,%3}, [%4];" \
        : "=r"(r0), "=r"(r1), "=r"(r2), "=r"(r3) : "r"(a))
#define MMA(c, a, b) \
    asm volatile("mma.sync.aligned.m16n8k16.row.col.f32.f16.f16.f32 " \
        "{%0,%1,%2,%3},{%4,%5,%6,%7},{%8,%9},{%0,%1,%2,%3};" \
        : "+f"(c[0]), "+f"(c[1]), "+f"(c[2]), "+f"(c[3]) \
        : "r"(a[0]), "r"(a[1]), "r"(a[2]), "r"(a[3]), "r"(b[0]), "r"(b[1]))

// ---------------- fused conversion + counter zero + output zero ----------------
struct CvtArgs {
    const float* s[5];
    __half* h[5];
    float* outz;
    int bend[6];   // 5 cvt regions + 1 zero region (cumulative block bounds)
};

__global__ void k_cvt_all(CvtArgs a) {
    if (blockIdx.x == 0 && threadIdx.x < 2 * E_) {
        if (threadIdx.x < E_) g_counts[threadIdx.x] = 0;
        else                  g_cursor[threadIdx.x - E_] = 0;
    }
    int b = blockIdx.x;
    int i = 0;
    while (i < 5 && b >= a.bend[i]) i++;
    int lb = b - (i ? a.bend[i - 1] : 0);
    int idx = lb * 256 + threadIdx.x;          // index of 8-elem chunk

    if (i == 5) {                               // zero the output buffer
        float4 z = make_float4(0.f, 0.f, 0.f, 0.f);
        ((float4*)a.outz)[idx * 2] = z;
        ((float4*)a.outz)[idx * 2 + 1] = z;
        return;
    }

    const float4* src = (const float4*)a.s[i];
    float4 v0 = src[idx * 2];
    float4 v1 = src[idx * 2 + 1];
    float f[8] = {v0.x, v0.y, v0.z, v0.w, v1.x, v1.y, v1.z, v1.w};
    uint32_t hp[4];
#pragma unroll
    for (int p = 0; p < 4; p++) {
        __half h0 = __float2half_rn(f[p * 2]);
        __half h1 = __float2half_rn(f[p * 2 + 1]);
        hp[p] = (uint32_t)__half_as_ushort(h0) | ((uint32_t)__half_as_ushort(h1) << 16);
    }
    ((uint4*)a.h[i])[idx] = make_uint4(hp[0], hp[1], hp[2], hp[3]);
}

// ---------------- gate (fp32, proven) ----------------
__global__ void k_gate(const float* __restrict__ x, const float* __restrict__ gw, int T) {
    __shared__ float sg[E_ * D_];
    const float4* gw4 = (const float4*)gw;
    float4* sg4 = (float4*)sg;
    for (int i = threadIdx.x; i < E_ * D_ / 4; i += blockDim.x) sg4[i] = gw4[i];
    __syncthreads();

    int wid = threadIdx.x >> 5, lane = threadIdx.x & 31;
    int t = blockIdx.x * 8 + wid;
    if (t >= T) return;

    float acc[E_];
#pragma unroll
    for (int e = 0; e < E_; e++) acc[e] = 0.f;
    const float4* xr = (const float4*)(x + (size_t)t * D_);
    for (int i = lane; i < D_ / 4; i += 32) {
        float4 xv = xr[i];
#pragma unroll
        for (int e = 0; e < E_; e++) {
            float4 g = sg4[e * (D_ / 4) + i];
            acc[e] += xv.x * g.x + xv.y * g.y + xv.z * g.z + xv.w * g.w;
        }
    }
#pragma unroll
    for (int e = 0; e < E_; e++)
#pragma unroll
        for (int o = 16; o > 0; o >>= 1) acc[e] += __shfl_xor_sync(0xffffffffu, acc[e], o);

    if (lane == 0) {
        float m = acc[0];
#pragma unroll
        for (int e = 1; e < E_; e++) m = fmaxf(m, acc[e]);
        float p[E_]; float s = 0.f;
#pragma unroll
        for (int e = 0; e < E_; e++) { p[e] = __expf(acc[e] - m); s += p[e]; }
        float inv = 1.f / s;
#pragma unroll
        for (int e = 0; e < E_; e++) p[e] *= inv;
        int i0 = 0; float v0 = p[0];
#pragma unroll
        for (int e = 1; e < E_; e++) if (p[e] > v0) { v0 = p[e]; i0 = e; }
        int i1 = -1; float v1 = -1.f;
#pragma unroll
        for (int e = 0; e < E_; e++) if (e != i0 && p[e] > v1) { v1 = p[e]; i1 = e; }
        g_top[t * 2] = i0;  g_top[t * 2 + 1] = i1;
        g_wgt[t * 2] = v0;  g_wgt[t * 2 + 1] = v1;
        atomicAdd(&g_counts[i0], 1);
        atomicAdd(&g_counts[i1], 1);
    }
}

// ---------------- scatter + offsets (fused) ----------------
__global__ void k_scatter(int T) {
    int i = blockIdx.x * blockDim.x + threadIdx.x;
    if (blockIdx.x == 0 && threadIdx.x == 0) {
        int s = 0;
        for (int e = 0; e < E_; e++) { g_offs[e] = s; s += g_counts[e]; }
        g_offs[E_] = s;
    }
    if (i >= T * 2) return;
    int t = i >> 1;
    int e = g_top[i];
    int off = 0;
#pragma unroll
    for (int j = 0; j < E_; j++) off += (j < e) ? g_counts[j] : 0;
    int pos = atomicAdd(&g_cursor[e], 1);
    g_bucket[off + pos] = t;
    g_bw[off + pos] = g_wgt[i];
}

// ======================================================================
// fc1 merged (routed + shared): fp16 GEMM, K-stage 64, double buffered.
// CTA: 128 rows x 64 features (128 interleaved y/g rows). SiLU fused.
// grid.y: [0,24) shared; [24,120) routed (e=(zy-24)/12).
// ======================================================================
__global__ __launch_bounds__(256)
void k_fc1(const __half* __restrict__ xq, const __half* __restrict__ W1q,
           const __half* __restrict__ S1q, __half* __restrict__ aRq,
           __half* __restrict__ aSq, int T) {
    extern __shared__ __half sm[];
    __shared__ int toks[128];

    int zy = blockIdx.y;
    bool routed = zy >= 24;
    int e = routed ? (zy - 24) / 12 : 0;
    int ytile = routed ? (zy - 24) % 12 : zy;
    int hid = routed ? H_ : HS_;
    const __half* W = routed ? W1q + (size_t)e * 2 * H_ * D_ : S1q;
    __half* Oq = routed ? aRq : aSq;
    int rbase = routed ? g_offs[e] : 0;
    int mcount = routed ? (g_offs[e + 1] - rbase) : T;
    int m0 = blockIdx.x * 128;
    if (m0 >= mcount) return;
    int n0f = ytile * 64;
    int tid = threadIdx.x;

    if (tid < 128) {
        int r = m0 + tid; if (r > mcount - 1) r = mcount - 1;
        toks[tid] = routed ? g_bucket[rbase + r] : r;
    }
    __syncthreads();

    uint32_t sbase = cvta_s(sm);
    const int K = D_;
    const int nst = K / KSZ;            // 16

    auto load_stage = [&](int s) {
        uint32_t sb = sbase + (uint32_t)(s & 1) * STAGEB;
        int k0 = s * KSZ;
#pragma unroll
        for (int j = 0; j < 8; j++) {
            int c = tid + 256 * j;
            int mat = c >> 10;            // 0=A, 1=B
            int rc = c & 1023;
            int row = rc >> 3;
            int ch = rc & 7;
            uint32_t dst = sb + (uint32_t)(mat * MATB + (row * STR + ch * 8) * 2);
            const __half* src;
            if (mat == 0) {
                src = xq + (size_t)toks[row] * K + k0 + ch * 8;
            } else {
                int f = n0f + (row >> 1);
                int srow = (row & 1) ? (hid + f) : f;
                src = W + (size_t)srow * K + k0 + ch * 8;
            }
            CPA(dst, src);
        }
        CPC();
    };

    int wid = tid >> 5, lane = tid & 31;
    int wm = wid >> 2, wn = wid & 3;

    float c[4][4][4];
#pragma unroll
    for (int a = 0; a < 4; a++)
#pragma unroll
        for (int b = 0; b < 4; b++)
#pragma unroll
            for (int d = 0; d < 4; d++) c[a][b][d] = 0.f;

    int arow = wm * 64 + (lane & 15);
    int acol0 = (lane >> 4) * 8;
    int g8 = lane >> 3;
    int brin = lane & 7;

    load_stage(0);
    for (int s = 0; s < nst; s++) {
        if (s + 1 < nst) { load_stage(s + 1); CPW1(); } else { CPW0(); }
        __syncthreads();
        uint32_t sb = sbase + (uint32_t)(s & 1) * STAGEB;
        uint32_t Ab = sb;
        uint32_t Bb = sb + MATB;
#pragma unroll
        for (int ks = 0; ks < 4; ks++) {
            uint32_t af[4][4], bf[4][2];
#pragma unroll
            for (int mi = 0; mi < 4; mi++) {
                uint32_t off = (uint32_t)((arow + mi * 16) * STR + ks * 16 + acol0) * 2;
                LDM4(af[mi][0], af[mi][1], af[mi][2], af[mi][3], Ab + off);
            }
#pragma unroll
            for (int j2 = 0; j2 < 2; j2++) {
                int nf = j2 * 2 + (g8 >> 1);
                uint32_t off = (uint32_t)((wn * 32 + nf * 8 + brin) * STR + ks * 16 + (g8 & 1) * 8) * 2;
                uint32_t r0, r1, r2, r3;
                LDM4(r0, r1, r2, r3, Bb + off);
                bf[j2 * 2][0] = r0; bf[j2 * 2][1] = r1; bf[j2 * 2 + 1][0] = r2; bf[j2 * 2 + 1][1] = r3;
            }
#pragma unroll
            for (int mi = 0; mi < 4; mi++)
#pragma unroll
                for (int nj = 0; nj < 4; nj++) MMA(c[mi][nj], af[mi], bf[nj]);
        }
        __syncthreads();
    }

    int rrem = mcount - m0;
#pragma unroll
    for (int mi = 0; mi < 4; mi++)
#pragma unroll
        for (int half = 0; half < 2; half++) {
            int row = wm * 64 + mi * 16 + (lane >> 2) + half * 8;
            if (row < rrem) {
                size_t rb = (size_t)(rbase + m0 + row) * hid;
#pragma unroll
                for (int nj = 0; nj < 4; nj++) {
                    float y = c[mi][nj][half * 2 + 0];
                    float g = c[mi][nj][half * 2 + 1];
                    float a = y * g / (1.f + __expf(-g));
                    int f = n0f + wn * 16 + nj * 4 + (lane & 3);
                    Oq[rb + f] = __float2half_rn(a);
                }
            }
        }
}

// ======================================================================
// fc2 merged (shared z=0 first, routed z=1..8): fp16 GEMM 128x128,
// K-stage 64, double buffered. Output pre-zeroed; both paths atomicAdd.
// ======================================================================
__global__ __launch_bounds__(256)
void k_fc2(const __half* __restrict__ aRq, const __half* __restrict__ aSq,
           const __half* __restrict__ W2q, const __half* __restrict__ S2q,
           float* __restrict__ out, int T) {
    extern __shared__ __half sm[];
    __shared__ int   toks[128];
    __shared__ int   etok[128];
    __shared__ float ew[128];

    int z = blockIdx.z;
    bool routed = z >= 1;
    int e = routed ? z - 1 : 0;
    int K = routed ? H_ : HS_;
    const __half* A = routed ? aRq : aSq;
    const __half* W = routed ? W2q + (size_t)e * D_ * H_ : S2q;
    int rbase = routed ? g_offs[e] : 0;
    int mcount = routed ? (g_offs[e + 1] - rbase) : T;
    int m0 = blockIdx.x * 128;
    if (m0 >= mcount) return;
    int n0 = blockIdx.y * 128;
    int tid = threadIdx.x;

    if (tid < 128) {
        int r = m0 + tid; if (r > mcount - 1) r = mcount - 1;
        toks[tid] = rbase + r;
        if (routed) { etok[tid] = g_bucket[rbase + r]; ew[tid] = g_bw[rbase + r]; }
        else        { etok[tid] = r;                   ew[tid] = 1.f; }
    }
    __syncthreads();

    uint32_t sbase = cvta_s(sm);
    const int nst = K / KSZ;            // 12 or 24

    auto load_stage = [&](int s) {
        uint32_t sb = sbase + (uint32_t)(s & 1) * STAGEB;
        int k0 = s * KSZ;
#pragma unroll
        for (int j = 0; j < 8; j++) {
            int c = tid + 256 * j;
            int mat = c >> 10;            // 0=A, 1=B
            int rc = c & 1023;
            int row = rc >> 3;
            int ch = rc & 7;
            uint32_t dst = sb + (uint32_t)(mat * MATB + (row * STR + ch * 8) * 2);
            const __half* src;
            if (mat == 0) {
                src = A + (size_t)toks[row] * K + k0 + ch * 8;
            } else {
                src = W + (size_t)(n0 + row) * K + k0 + ch * 8;
            }
            CPA(dst, src);
        }
        CPC();
    };

    int wid = tid >> 5, lane = tid & 31;
    int wm = wid >> 2, wn = wid & 3;

    float c[4][4][4];
#pragma unroll
    for (int a = 0; a < 4; a++)
#pragma unroll
        for (int b = 0; b < 4; b++)
#pragma unroll
            for (int d = 0; d < 4; d++) c[a][b][d] = 0.f;

    int arow = wm * 64 + (lane & 15);
    int acol0 = (lane >> 4) * 8;
    int g8 = lane >> 3;
    int brin = lane & 7;

    load_stage(0);
    for (int s = 0; s < nst; s++) {
        if (s + 1 < nst) { load_stage(s + 1); CPW1(); } else { CPW0(); }
        __syncthreads();
        uint32_t sb = sbase + (uint32_t)(s & 1) * STAGEB;
        uint32_t Ab = sb;
        uint32_t Bb = sb + MATB;
#pragma unroll
        for (int ks = 0; ks < 4; ks++) {
            uint32_t af[4][4], bf[4][2];
#pragma unroll
            for (int mi = 0; mi < 4; mi++) {
                uint32_t off = (uint32_t)((arow + mi * 16) * STR + ks * 16 + acol0) * 2;
                LDM4(af[mi][0], af[mi][1], af[mi][2], af[mi][3], Ab + off);
            }
#pragma unroll
            for (int j2 = 0; j2 < 2; j2++) {
                int nf = j2 * 2 + (g8 >> 1);
                uint32_t off = (uint32_t)((wn * 32 + nf * 8 + brin) * STR + ks * 16 + (g8 & 1) * 8) * 2;
                uint32_t r0, r1, r2, r3;
                LDM4(r0, r1, r2, r3, Bb + off);
                bf[j2 * 2][0] = r0; bf[j2 * 2][1] = r1; bf[j2 * 2 + 1][0] = r2; bf[j2 * 2 + 1][1] = r3;
            }
#pragma unroll
            for (int mi = 0; mi < 4; mi++)
#pragma unroll
                for (int nj = 0; nj < 4; nj++) MMA(c[mi][nj], af[mi], bf[nj]);
        }
        __syncthreads();
    }

    int rrem = mcount - m0;
#pragma unroll
    for (int mi = 0; mi < 4; mi++)
#pragma unroll
        for (int half = 0; half < 2; half++) {
            int row = wm * 64 + mi * 16 + (lane >> 2) + half * 8;
            if (row < rrem) {
                int t = etok[row]; float w = ew[row];
                float* base = out + (size_t)t * D_;
#pragma unroll
                for (int nj = 0; nj < 4; nj++) {
                    int col = n0 + wn * 32 + nj * 8 + (lane & 3) * 2;
                    atomicAdd(base + col,     w * c[mi][nj][half * 2 + 0]);
                    atomicAdd(base + col + 1, w * c[mi][nj][half * 2 + 1]);
                }
            }
        }
}

// ---------------- launcher ----------------
extern "C" void kernel_launch(void* const* d_in, const int* in_sizes, int n_in,
                              void* d_out, int out_size) {
    const float* x   = (const float*)d_in[0];
    const float* gw  = (const float*)d_in[1];
    const float* W1  = (const float*)d_in[2];
    const float* W2  = (const float*)d_in[3];
    const float* Ws1 = (const float*)d_in[4];
    const float* Ws2 = (const float*)d_in[5];
    float* out = (float*)d_out;

    int T = in_sizes[0] / D_;
    if (T > TMAX) T = TMAX;

    __half *xq, *W1q, *W2q, *S1q, *S2q, *aRq, *aSq;
    cudaGetSymbolAddress((void**)&xq,  g_xq);
    cudaGetSymbolAddress((void**)&W1q, g_W1q);
    cudaGetSymbolAddress((void**)&W2q, g_W2q);
    cudaGetSymbolAddress((void**)&S1q, g_S1q);
    cudaGetSymbolAddress((void**)&S2q, g_S2q);
    cudaGetSymbolAddress((void**)&aRq, g_aRq);
    cudaGetSymbolAddress((void**)&aSq, g_aSq);

    cudaFuncSetAttribute(k_fc1, cudaFuncAttributeMaxDynamicSharedMemorySize, SMEM_BYTES);
    cudaFuncSetAttribute(k_fc2, cudaFuncAttributeMaxDynamicSharedMemorySize, SMEM_BYTES);

    // fused conversion + counter zero + output zero (single launch)
    CvtArgs ca;
    ca.s[0] = x;   ca.h[0] = xq;
    ca.s[1] = W1;  ca.h[1] = W1q;
    ca.s[2] = W2;  ca.h[2] = W2q;
    ca.s[3] = Ws1; ca.h[3] = S1q;
    ca.s[4] = Ws2; ca.h[4] = S2q;
    ca.outz = out;
    int nb[6] = {
        (T * D_ / 8) / 256,
        (E_ * 2 * H_ * D_ / 8) / 256,
        (E_ * D_ * H_ / 8) / 256,
        (2 * HS_ * D_ / 8) / 256,
        (D_ * HS_ / 8) / 256,
        (T * D_ / 8) / 256            // output zeroing region
    };
    int cum = 0;
    for (int i = 0; i < 6; i++) { cum += nb[i]; ca.bend[i] = cum; }
    k_cvt_all<<<cum, 256>>>(ca);

    // routing: gate, then scatter (offsets fused into scatter)
    k_gate<<<(T + 7) / 8, 256>>>(x, gw, T);
    k_scatter<<<(T * 2 + 255) / 256, 256>>>(T);

    int mt = (T + 127) / 128;

    // fc1 merged: 24 shared tiles + 96 routed tiles in one launch
    k_fc1<<<dim3(mt, 120), 256, SMEM_BYTES>>>(xq, W1q, S1q, aRq, aSq, T);

    // fc2 merged: shared (z=0, scheduled first) + routed (z=1..8)
    k_fc2<<<dim3(mt, D_ / 128, 1 + E_), 256, SMEM_BYTES>>>(aRq, aSq, W2q, S2q, out, T);
}

// round 16
// speedup vs baseline: 1.9397x; 1.0274x over previous
#include <cuda_runtime.h>
#include <cuda_fp16.h>
#include <stdint.h>

#define D_    1024
#define H_    768
#define HS_   1536
#define E_    8
#define TMAX  2048
#define AMAX  (TMAX*2)

#define KSZ   64
#define STR   72                      // smem row stride in fp16 elems (144B; 8 rows -> 8 distinct 16B banks)
#define MATB  (128*STR*2)             // 18432 B per matrix tile (128 rows x 64 elems + pad)
#define STAGEB (2*MATB)               // A, B -> 36864 B
#define NSTAGE 3
#define SMEM_BYTES (NSTAGE*STAGEB)    // 110592 B, triple buffered (2 CTAs/SM: 221 KB <= 228 KB)

// ---------------- routing scratch ----------------
__device__ int   g_counts[E_];
__device__ int   g_offs[E_ + 1];
__device__ int   g_cursor[E_];
__device__ int   g_top[AMAX];
__device__ float g_wgt[AMAX];
__device__ int   g_bucket[AMAX];
__device__ float g_bw[AMAX];

// ---------------- fp16 operand scratch ----------------
__device__ __align__(16) __half g_xq[TMAX * D_];
__device__ __align__(16) __half g_W1q[E_ * 2 * H_ * D_];
__device__ __align__(16) __half g_W2q[E_ * D_ * H_];
__device__ __align__(16) __half g_S1q[2 * HS_ * D_];
__device__ __align__(16) __half g_S2q[D_ * HS_];
__device__ __align__(16) __half g_aRq[AMAX * H_];
__device__ __align__(16) __half g_aSq[TMAX * HS_];

// ---------------- PTX helpers ----------------
__device__ __forceinline__ uint32_t cvta_s(const void* p) {
    return (uint32_t)__cvta_generic_to_shared(p);
}
#define CPA(dst, src) asm volatile("cp.async.cg.shared.global [%0], [%1], 16;\n" :: "r"(dst), "l"(src))
#define CPC() asm volatile("cp.async.commit_group;\n")
#define CPW1() asm volatile("cp.async.wait_group 1;\n")
#define CPW0() asm volatile("cp.async.wait_group 0;\n")
#define LDM4(r0, r1, r2, r3, a) \
    asm volatile("ldmatrix.sync.aligned.m8n8.x4.shared.b16 {%0,%1,%2,%3}, [%4];" \
        : "=r"(r0), "=r"(r1), "=r"(r2), "=r"(r3) : "r"(a))
#define MMA(c, a, b) \
    asm volatile("mma.sync.aligned.m16n8k16.row.col.f32.f16.f16.f32 " \
        "{%0,%1,%2,%3},{%4,%5,%6,%7},{%8,%9},{%0,%1,%2,%3};" \
        : "+f"(c[0]), "+f"(c[1]), "+f"(c[2]), "+f"(c[3]) \
        : "r"(a[0]), "r"(a[1]), "r"(a[2]), "r"(a[3]), "r"(b[0]), "r"(b[1]))

// ---------------- fused conversion + counter zero + output zero ----------------
struct CvtArgs {
    const float* s[5];
    __half* h[5];
    float* outz;
    int bend[6];   // 5 cvt regions + 1 zero region (cumulative block bounds)
};

__global__ void k_cvt_all(CvtArgs a) {
    if (blockIdx.x == 0 && threadIdx.x < 2 * E_) {
        if (threadIdx.x < E_) g_counts[threadIdx.x] = 0;
        else                  g_cursor[threadIdx.x - E_] = 0;
    }
    int b = blockIdx.x;
    int i = 0;
    while (i < 5 && b >= a.bend[i]) i++;
    int lb = b - (i ? a.bend[i - 1] : 0);
    int idx = lb * 256 + threadIdx.x;          // index of 8-elem chunk

    if (i == 5) {                               // zero the output buffer
        float4 z = make_float4(0.f, 0.f, 0.f, 0.f);
        ((float4*)a.outz)[idx * 2] = z;
        ((float4*)a.outz)[idx * 2 + 1] = z;
        return;
    }

    const float4* src = (const float4*)a.s[i];
    float4 v0 = src[idx * 2];
    float4 v1 = src[idx * 2 + 1];
    float f[8] = {v0.x, v0.y, v0.z, v0.w, v1.x, v1.y, v1.z, v1.w};
    uint32_t hp[4];
#pragma unroll
    for (int p = 0; p < 4; p++) {
        __half h0 = __float2half_rn(f[p * 2]);
        __half h1 = __float2half_rn(f[p * 2 + 1]);
        hp[p] = (uint32_t)__half_as_ushort(h0) | ((uint32_t)__half_as_ushort(h1) << 16);
    }
    ((uint4*)a.h[i])[idx] = make_uint4(hp[0], hp[1], hp[2], hp[3]);
}

// ---------------- gate (fp32, proven) ----------------
__global__ void k_gate(const float* __restrict__ x, const float* __restrict__ gw, int T) {
    __shared__ float sg[E_ * D_];
    const float4* gw4 = (const float4*)gw;
    float4* sg4 = (float4*)sg;
    for (int i = threadIdx.x; i < E_ * D_ / 4; i += blockDim.x) sg4[i] = gw4[i];
    __syncthreads();

    int wid = threadIdx.x >> 5, lane = threadIdx.x & 31;
    int t = blockIdx.x * 8 + wid;
    if (t >= T) return;

    float acc[E_];
#pragma unroll
    for (int e = 0; e < E_; e++) acc[e] = 0.f;
    const float4* xr = (const float4*)(x + (size_t)t * D_);
    for (int i = lane; i < D_ / 4; i += 32) {
        float4 xv = xr[i];
#pragma unroll
        for (int e = 0; e < E_; e++) {
            float4 g = sg4[e * (D_ / 4) + i];
            acc[e] += xv.x * g.x + xv.y * g.y + xv.z * g.z + xv.w * g.w;
        }
    }
#pragma unroll
    for (int e = 0; e < E_; e++)
#pragma unroll
        for (int o = 16; o > 0; o >>= 1) acc[e] += __shfl_xor_sync(0xffffffffu, acc[e], o);

    if (lane == 0) {
        float m = acc[0];
#pragma unroll
        for (int e = 1; e < E_; e++) m = fmaxf(m, acc[e]);
        float p[E_]; float s = 0.f;
#pragma unroll
        for (int e = 0; e < E_; e++) { p[e] = __expf(acc[e] - m); s += p[e]; }
        float inv = 1.f / s;
#pragma unroll
        for (int e = 0; e < E_; e++) p[e] *= inv;
        int i0 = 0; float v0 = p[0];
#pragma unroll
        for (int e = 1; e < E_; e++) if (p[e] > v0) { v0 = p[e]; i0 = e; }
        int i1 = -1; float v1 = -1.f;
#pragma unroll
        for (int e = 0; e < E_; e++) if (e != i0 && p[e] > v1) { v1 = p[e]; i1 = e; }
        g_top[t * 2] = i0;  g_top[t * 2 + 1] = i1;
        g_wgt[t * 2] = v0;  g_wgt[t * 2 + 1] = v1;
        atomicAdd(&g_counts[i0], 1);
        atomicAdd(&g_counts[i1], 1);
    }
}

// ---------------- scatter + offsets (fused) ----------------
__global__ void k_scatter(int T) {
    int i = blockIdx.x * blockDim.x + threadIdx.x;
    if (blockIdx.x == 0 && threadIdx.x == 0) {
        int s = 0;
        for (int e = 0; e < E_; e++) { g_offs[e] = s; s += g_counts[e]; }
        g_offs[E_] = s;
    }
    if (i >= T * 2) return;
    int t = i >> 1;
    int e = g_top[i];
    int off = 0;
#pragma unroll
    for (int j = 0; j < E_; j++) off += (j < e) ? g_counts[j] : 0;
    int pos = atomicAdd(&g_cursor[e], 1);
    g_bucket[off + pos] = t;
    g_bw[off + pos] = g_wgt[i];
}

// ======================================================================
// fc1 merged (routed + shared): fp16 GEMM, K-stage 64, 3-stage pipeline,
// ONE barrier per stage. CTA: 128 rows x 64 features. SiLU fused.
// grid.y: [0,24) shared; [24,120) routed (e=(zy-24)/12).
// ======================================================================
__global__ __launch_bounds__(256)
void k_fc1(const __half* __restrict__ xq, const __half* __restrict__ W1q,
           const __half* __restrict__ S1q, __half* __restrict__ aRq,
           __half* __restrict__ aSq, int T) {
    extern __shared__ __half sm[];
    __shared__ int toks[128];

    int zy = blockIdx.y;
    bool routed = zy >= 24;
    int e = routed ? (zy - 24) / 12 : 0;
    int ytile = routed ? (zy - 24) % 12 : zy;
    int hid = routed ? H_ : HS_;
    const __half* W = routed ? W1q + (size_t)e * 2 * H_ * D_ : S1q;
    __half* Oq = routed ? aRq : aSq;
    int rbase = routed ? g_offs[e] : 0;
    int mcount = routed ? (g_offs[e + 1] - rbase) : T;
    int m0 = blockIdx.x * 128;
    if (m0 >= mcount) return;
    int n0f = ytile * 64;
    int tid = threadIdx.x;

    if (tid < 128) {
        int r = m0 + tid; if (r > mcount - 1) r = mcount - 1;
        toks[tid] = routed ? g_bucket[rbase + r] : r;
    }
    __syncthreads();

    uint32_t sbase = cvta_s(sm);
    const int K = D_;
    const int nst = K / KSZ;            // 16

    auto load_stage = [&](int s) {
        uint32_t sb = sbase + (uint32_t)(s % NSTAGE) * STAGEB;
        int k0 = s * KSZ;
#pragma unroll
        for (int j = 0; j < 8; j++) {
            int c = tid + 256 * j;
            int mat = c >> 10;            // 0=A, 1=B
            int rc = c & 1023;
            int row = rc >> 3;
            int ch = rc & 7;
            uint32_t dst = sb + (uint32_t)(mat * MATB + (row * STR + ch * 8) * 2);
            const __half* src;
            if (mat == 0) {
                src = xq + (size_t)toks[row] * K + k0 + ch * 8;
            } else {
                int f = n0f + (row >> 1);
                int srow = (row & 1) ? (hid + f) : f;
                src = W + (size_t)srow * K + k0 + ch * 8;
            }
            CPA(dst, src);
        }
        CPC();
    };

    int wid = tid >> 5, lane = tid & 31;
    int wm = wid >> 2, wn = wid & 3;

    float c[4][4][4];
#pragma unroll
    for (int a = 0; a < 4; a++)
#pragma unroll
        for (int b = 0; b < 4; b++)
#pragma unroll
            for (int d = 0; d < 4; d++) c[a][b][d] = 0.f;

    int arow = wm * 64 + (lane & 15);
    int acol0 = (lane >> 4) * 8;
    int g8 = lane >> 3;
    int brin = lane & 7;

    load_stage(0);
    load_stage(1);
    for (int s = 0; s < nst; s++) {
        if (s + 1 < nst) { CPW1(); } else { CPW0(); }
        __syncthreads();            // single barrier: orders prev-stage reads before load(s+2) writes
        uint32_t sb = sbase + (uint32_t)(s % NSTAGE) * STAGEB;
        uint32_t Ab = sb;
        uint32_t Bb = sb + MATB;
#pragma unroll
        for (int ks = 0; ks < 4; ks++) {
            uint32_t af[4][4], bf[4][2];
#pragma unroll
            for (int mi = 0; mi < 4; mi++) {
                uint32_t off = (uint32_t)((arow + mi * 16) * STR + ks * 16 + acol0) * 2;
                LDM4(af[mi][0], af[mi][1], af[mi][2], af[mi][3], Ab + off);
            }
#pragma unroll
            for (int j2 = 0; j2 < 2; j2++) {
                int nf = j2 * 2 + (g8 >> 1);
                uint32_t off = (uint32_t)((wn * 32 + nf * 8 + brin) * STR + ks * 16 + (g8 & 1) * 8) * 2;
                uint32_t r0, r1, r2, r3;
                LDM4(r0, r1, r2, r3, Bb + off);
                bf[j2 * 2][0] = r0; bf[j2 * 2][1] = r1; bf[j2 * 2 + 1][0] = r2; bf[j2 * 2 + 1][1] = r3;
            }
#pragma unroll
            for (int mi = 0; mi < 4; mi++)
#pragma unroll
                for (int nj = 0; nj < 4; nj++) MMA(c[mi][nj], af[mi], bf[nj]);
        }
        if (s + 2 < nst) load_stage(s + 2);
    }

    int rrem = mcount - m0;
#pragma unroll
    for (int mi = 0; mi < 4; mi++)
#pragma unroll
        for (int half = 0; half < 2; half++) {
            int row = wm * 64 + mi * 16 + (lane >> 2) + half * 8;
            if (row < rrem) {
                size_t rb = (size_t)(rbase + m0 + row) * hid;
#pragma unroll
                for (int nj = 0; nj < 4; nj++) {
                    float y = c[mi][nj][half * 2 + 0];
                    float g = c[mi][nj][half * 2 + 1];
                    float a = y * g / (1.f + __expf(-g));
                    int f = n0f + wn * 16 + nj * 4 + (lane & 3);
                    Oq[rb + f] = __float2half_rn(a);
                }
            }
        }
}

// ======================================================================
// fc2 merged (shared z=0 first, routed z=1..8): fp16 GEMM 128x128,
// K-stage 64, 3-stage pipeline, one barrier per stage. Both paths atomicAdd.
// ======================================================================
__global__ __launch_bounds__(256)
void k_fc2(const __half* __restrict__ aRq, const __half* __restrict__ aSq,
           const __half* __restrict__ W2q, const __half* __restrict__ S2q,
           float* __restrict__ out, int T) {
    extern __shared__ __half sm[];
    __shared__ int   toks[128];
    __shared__ int   etok[128];
    __shared__ float ew[128];

    int z = blockIdx.z;
    bool routed = z >= 1;
    int e = routed ? z - 1 : 0;
    int K = routed ? H_ : HS_;
    const __half* A = routed ? aRq : aSq;
    const __half* W = routed ? W2q + (size_t)e * D_ * H_ : S2q;
    int rbase = routed ? g_offs[e] : 0;
    int mcount = routed ? (g_offs[e + 1] - rbase) : T;
    int m0 = blockIdx.x * 128;
    if (m0 >= mcount) return;
    int n0 = blockIdx.y * 128;
    int tid = threadIdx.x;

    if (tid < 128) {
        int r = m0 + tid; if (r > mcount - 1) r = mcount - 1;
        toks[tid] = rbase + r;
        if (routed) { etok[tid] = g_bucket[rbase + r]; ew[tid] = g_bw[rbase + r]; }
        else        { etok[tid] = r;                   ew[tid] = 1.f; }
    }
    __syncthreads();

    uint32_t sbase = cvta_s(sm);
    const int nst = K / KSZ;            // 12 or 24

    auto load_stage = [&](int s) {
        uint32_t sb = sbase + (uint32_t)(s % NSTAGE) * STAGEB;
        int k0 = s * KSZ;
#pragma unroll
        for (int j = 0; j < 8; j++) {
            int c = tid + 256 * j;
            int mat = c >> 10;            // 0=A, 1=B
            int rc = c & 1023;
            int row = rc >> 3;
            int ch = rc & 7;
            uint32_t dst = sb + (uint32_t)(mat * MATB + (row * STR + ch * 8) * 2);
            const __half* src;
            if (mat == 0) {
                src = A + (size_t)toks[row] * K + k0 + ch * 8;
            } else {
                src = W + (size_t)(n0 + row) * K + k0 + ch * 8;
            }
            CPA(dst, src);
        }
        CPC();
    };

    int wid = tid >> 5, lane = tid & 31;
    int wm = wid >> 2, wn = wid & 3;

    float c[4][4][4];
#pragma unroll
    for (int a = 0; a < 4; a++)
#pragma unroll
        for (int b = 0; b < 4; b++)
#pragma unroll
            for (int d = 0; d < 4; d++) c[a][b][d] = 0.f;

    int arow = wm * 64 + (lane & 15);
    int acol0 = (lane >> 4) * 8;
    int g8 = lane >> 3;
    int brin = lane & 7;

    load_stage(0);
    load_stage(1);
    for (int s = 0; s < nst; s++) {
        if (s + 1 < nst) { CPW1(); } else { CPW0(); }
        __syncthreads();
        uint32_t sb = sbase + (uint32_t)(s % NSTAGE) * STAGEB;
        uint32_t Ab = sb;
        uint32_t Bb = sb + MATB;
#pragma unroll
        for (int ks = 0; ks < 4; ks++) {
            uint32_t af[4][4], bf[4][2];
#pragma unroll
            for (int mi = 0; mi < 4; mi++) {
                uint32_t off = (uint32_t)((arow + mi * 16) * STR + ks * 16 + acol0) * 2;
                LDM4(af[mi][0], af[mi][1], af[mi][2], af[mi][3], Ab + off);
            }
#pragma unroll
            for (int j2 = 0; j2 < 2; j2++) {
                int nf = j2 * 2 + (g8 >> 1);
                uint32_t off = (uint32_t)((wn * 32 + nf * 8 + brin) * STR + ks * 16 + (g8 & 1) * 8) * 2;
                uint32_t r0, r1, r2, r3;
                LDM4(r0, r1, r2, r3, Bb + off);
                bf[j2 * 2][0] = r0; bf[j2 * 2][1] = r1; bf[j2 * 2 + 1][0] = r2; bf[j2 * 2 + 1][1] = r3;
            }
#pragma unroll
            for (int mi = 0; mi < 4; mi++)
#pragma unroll
                for (int nj = 0; nj < 4; nj++) MMA(c[mi][nj], af[mi], bf[nj]);
        }
        if (s + 2 < nst) load_stage(s + 2);
    }

    int rrem = mcount - m0;
#pragma unroll
    for (int mi = 0; mi < 4; mi++)
#pragma unroll
        for (int half = 0; half < 2; half++) {
            int row = wm * 64 + mi * 16 + (lane >> 2) + half * 8;
            if (row < rrem) {
                int t = etok[row]; float w = ew[row];
                float* base = out + (size_t)t * D_;
#pragma unroll
                for (int nj = 0; nj < 4; nj++) {
                    int col = n0 + wn * 32 + nj * 8 + (lane & 3) * 2;
                    atomicAdd(base + col,     w * c[mi][nj][half * 2 + 0]);
                    atomicAdd(base + col + 1, w * c[mi][nj][half * 2 + 1]);
                }
            }
        }
}

// ---------------- launcher ----------------
extern "C" void kernel_launch(void* const* d_in, const int* in_sizes, int n_in,
                              void* d_out, int out_size) {
    const float* x   = (const float*)d_in[0];
    const float* gw  = (const float*)d_in[1];
    const float* W1  = (const float*)d_in[2];
    const float* W2  = (const float*)d_in[3];
    const float* Ws1 = (const float*)d_in[4];
    const float* Ws2 = (const float*)d_in[5];
    float* out = (float*)d_out;

    int T = in_sizes[0] / D_;
    if (T > TMAX) T = TMAX;

    __half *xq, *W1q, *W2q, *S1q, *S2q, *aRq, *aSq;
    cudaGetSymbolAddress((void**)&xq,  g_xq);
    cudaGetSymbolAddress((void**)&W1q, g_W1q);
    cudaGetSymbolAddress((void**)&W2q, g_W2q);
    cudaGetSymbolAddress((void**)&S1q, g_S1q);
    cudaGetSymbolAddress((void**)&S2q, g_S2q);
    cudaGetSymbolAddress((void**)&aRq, g_aRq);
    cudaGetSymbolAddress((void**)&aSq, g_aSq);

    cudaFuncSetAttribute(k_fc1, cudaFuncAttributeMaxDynamicSharedMemorySize, SMEM_BYTES);
    cudaFuncSetAttribute(k_fc2, cudaFuncAttributeMaxDynamicSharedMemorySize, SMEM_BYTES);

    // fused conversion + counter zero + output zero (single launch)
    CvtArgs ca;
    ca.s[0] = x;   ca.h[0] = xq;
    ca.s[1] = W1;  ca.h[1] = W1q;
    ca.s[2] = W2;  ca.h[2] = W2q;
    ca.s[3] = Ws1; ca.h[3] = S1q;
    ca.s[4] = Ws2; ca.h[4] = S2q;
    ca.outz = out;
    int nb[6] = {
        (T * D_ / 8) / 256,
        (E_ * 2 * H_ * D_ / 8) / 256,
        (E_ * D_ * H_ / 8) / 256,
        (2 * HS_ * D_ / 8) / 256,
        (D_ * HS_ / 8) / 256,
        (T * D_ / 8) / 256            // output zeroing region
    };
    int cum = 0;
    for (int i = 0; i < 6; i++) { cum += nb[i]; ca.bend[i] = cum; }
    k_cvt_all<<<cum, 256>>>(ca);

    // routing: gate, then scatter (offsets fused into scatter)
    k_gate<<<(T + 7) / 8, 256>>>(x, gw, T);
    k_scatter<<<(T * 2 + 255) / 256, 256>>>(T);

    int mt = (T + 127) / 128;

    // fc1 merged: 24 shared tiles + 96 routed tiles in one launch
    k_fc1<<<dim3(mt, 120), 256, SMEM_BYTES>>>(xq, W1q, S1q, aRq, aSq, T);

    // fc2 merged: shared (z=0, scheduled first) + routed (z=1..8)
    k_fc2<<<dim3(mt, D_ / 128, 1 + E_), 256, SMEM_BYTES>>>(aRq, aSq, W2q, S2q, out, T);
}

// round 17
// speedup vs baseline: 2.0165x; 1.0396x over previous
#include <cuda_runtime.h>
#include <cuda_fp16.h>
#include <stdint.h>

#define D_    1024
#define H_    768
#define HS_   1536
#define E_    8
#define TMAX  2048
#define AMAX  (TMAX*2)

#define KSZ   64
#define STR   72                      // smem row stride in fp16 elems (144B; 8 rows -> 8 distinct 16B banks)
#define MATB  (128*STR*2)             // 18432 B per matrix tile (128 rows x 64 elems + pad)
#define STAGEB (2*MATB)               // A, B -> 36864 B
#define NSTAGE 3
#define SMEM_BYTES (NSTAGE*STAGEB)    // 110592 B, triple buffered (2 CTAs/SM: 221 KB <= 228 KB)

// ---------------- routing scratch ----------------
__device__ int   g_counts[E_];
__device__ int   g_offs[E_ + 1];
__device__ int   g_cursor[E_];
__device__ int   g_top[AMAX];
__device__ float g_wgt[AMAX];
__device__ int   g_bucket[AMAX];
__device__ float g_bw[AMAX];

// ---------------- fp16 operand scratch ----------------
__device__ __align__(16) __half g_xq[TMAX * D_];
__device__ __align__(16) __half g_W1q[E_ * 2 * H_ * D_];
__device__ __align__(16) __half g_W2q[E_ * D_ * H_];
__device__ __align__(16) __half g_S1q[2 * HS_ * D_];
__device__ __align__(16) __half g_S2q[D_ * HS_];
__device__ __align__(16) __half g_aRq[AMAX * H_];
__device__ __align__(16) __half g_aSq[TMAX * HS_];

// ---------------- PTX helpers ----------------
__device__ __forceinline__ uint32_t cvta_s(const void* p) {
    return (uint32_t)__cvta_generic_to_shared(p);
}
#define CPA(dst, src) asm volatile("cp.async.cg.shared.global [%0], [%1], 16;\n" :: "r"(dst), "l"(src))
#define CPC() asm volatile("cp.async.commit_group;\n")
#define CPW1() asm volatile("cp.async.wait_group 1;\n")
#define CPW0() asm volatile("cp.async.wait_group 0;\n")
#define LDM4(r0, r1, r2, r3, a) \
    asm volatile("ldmatrix.sync.aligned.m8n8.x4.shared.b16 {%0,%1,%2,%3}, [%4];" \
        : "=r"(r0), "=r"(r1), "=r"(r2), "=r"(r3) : "r"(a))
#define MMA(c, a, b) \
    asm volatile("mma.sync.aligned.m16n8k16.row.col.f32.f16.f16.f32 " \
        "{%0,%1,%2,%3},{%4,%5,%6,%7},{%8,%9},{%0,%1,%2,%3};" \
        : "+f"(c[0]), "+f"(c[1]), "+f"(c[2]), "+f"(c[3]) \
        : "r"(a[0]), "r"(a[1]), "r"(a[2]), "r"(a[3]), "r"(b[0]), "r"(b[1]))

// ---------------- fused conversion + counter zero + output zero ----------------
struct CvtArgs {
    const float* s[5];
    __half* h[5];
    float* outz;
    int bend[6];   // 5 cvt regions + 1 zero region (cumulative block bounds)
};

__global__ void k_cvt_all(CvtArgs a) {
    if (blockIdx.x == 0 && threadIdx.x < 2 * E_) {
        if (threadIdx.x < E_) g_counts[threadIdx.x] = 0;
        else                  g_cursor[threadIdx.x - E_] = 0;
    }
    int b = blockIdx.x;
    int i = 0;
    while (i < 5 && b >= a.bend[i]) i++;
    int lb = b - (i ? a.bend[i - 1] : 0);
    int idx = lb * 256 + threadIdx.x;          // index of 8-elem chunk

    if (i == 5) {                               // zero the output buffer
        float4 z = make_float4(0.f, 0.f, 0.f, 0.f);
        ((float4*)a.outz)[idx * 2] = z;
        ((float4*)a.outz)[idx * 2 + 1] = z;
        return;
    }

    const float4* src = (const float4*)a.s[i];
    float4 v0 = src[idx * 2];
    float4 v1 = src[idx * 2 + 1];
    float f[8] = {v0.x, v0.y, v0.z, v0.w, v1.x, v1.y, v1.z, v1.w};
    uint32_t hp[4];
#pragma unroll
    for (int p = 0; p < 4; p++) {
        __half h0 = __float2half_rn(f[p * 2]);
        __half h1 = __float2half_rn(f[p * 2 + 1]);
        hp[p] = (uint32_t)__half_as_ushort(h0) | ((uint32_t)__half_as_ushort(h1) << 16);
    }
    ((uint4*)a.h[i])[idx] = make_uint4(hp[0], hp[1], hp[2], hp[3]);
}

// ---------------- gate (fp32, proven) ----------------
__global__ void k_gate(const float* __restrict__ x, const float* __restrict__ gw, int T) {
    __shared__ float sg[E_ * D_];
    const float4* gw4 = (const float4*)gw;
    float4* sg4 = (float4*)sg;
    for (int i = threadIdx.x; i < E_ * D_ / 4; i += blockDim.x) sg4[i] = gw4[i];
    __syncthreads();

    int wid = threadIdx.x >> 5, lane = threadIdx.x & 31;
    int t = blockIdx.x * 8 + wid;
    if (t >= T) return;

    float acc[E_];
#pragma unroll
    for (int e = 0; e < E_; e++) acc[e] = 0.f;
    const float4* xr = (const float4*)(x + (size_t)t * D_);
    for (int i = lane; i < D_ / 4; i += 32) {
        float4 xv = xr[i];
#pragma unroll
        for (int e = 0; e < E_; e++) {
            float4 g = sg4[e * (D_ / 4) + i];
            acc[e] += xv.x * g.x + xv.y * g.y + xv.z * g.z + xv.w * g.w;
        }
    }
#pragma unroll
    for (int e = 0; e < E_; e++)
#pragma unroll
        for (int o = 16; o > 0; o >>= 1) acc[e] += __shfl_xor_sync(0xffffffffu, acc[e], o);

    if (lane == 0) {
        float m = acc[0];
#pragma unroll
        for (int e = 1; e < E_; e++) m = fmaxf(m, acc[e]);
        float p[E_]; float s = 0.f;
#pragma unroll
        for (int e = 0; e < E_; e++) { p[e] = __expf(acc[e] - m); s += p[e]; }
        float inv = 1.f / s;
#pragma unroll
        for (int e = 0; e < E_; e++) p[e] *= inv;
        int i0 = 0; float v0 = p[0];
#pragma unroll
        for (int e = 1; e < E_; e++) if (p[e] > v0) { v0 = p[e]; i0 = e; }
        int i1 = -1; float v1 = -1.f;
#pragma unroll
        for (int e = 0; e < E_; e++) if (e != i0 && p[e] > v1) { v1 = p[e]; i1 = e; }
        g_top[t * 2] = i0;  g_top[t * 2 + 1] = i1;
        g_wgt[t * 2] = v0;  g_wgt[t * 2 + 1] = v1;
        atomicAdd(&g_counts[i0], 1);
        atomicAdd(&g_counts[i1], 1);
    }
}

// ---------------- scatter + offsets (fused) ----------------
__global__ void k_scatter(int T) {
    int i = blockIdx.x * blockDim.x + threadIdx.x;
    if (blockIdx.x == 0 && threadIdx.x == 0) {
        int s = 0;
        for (int e = 0; e < E_; e++) { g_offs[e] = s; s += g_counts[e]; }
        g_offs[E_] = s;
    }
    if (i >= T * 2) return;
    int t = i >> 1;
    int e = g_top[i];
    int off = 0;
#pragma unroll
    for (int j = 0; j < E_; j++) off += (j < e) ? g_counts[j] : 0;
    int pos = atomicAdd(&g_cursor[e], 1);
    g_bucket[off + pos] = t;
    g_bw[off + pos] = g_wgt[i];
}

// ======================================================================
// fc1 merged (routed + shared): fp16 GEMM, K-stage 64, 3-stage smem
// pipeline + register double-buffered fragments. One barrier per stage.
// CTA: 128 rows x 64 features. SiLU fused.
// grid.y: [0,24) shared; [24,120) routed (e=(zy-24)/12).
// ======================================================================
__global__ __launch_bounds__(256, 2)
void k_fc1(const __half* __restrict__ xq, const __half* __restrict__ W1q,
           const __half* __restrict__ S1q, __half* __restrict__ aRq,
           __half* __restrict__ aSq, int T) {
    extern __shared__ __half sm[];
    __shared__ int toks[128];

    int zy = blockIdx.y;
    bool routed = zy >= 24;
    int e = routed ? (zy - 24) / 12 : 0;
    int ytile = routed ? (zy - 24) % 12 : zy;
    int hid = routed ? H_ : HS_;
    const __half* W = routed ? W1q + (size_t)e * 2 * H_ * D_ : S1q;
    __half* Oq = routed ? aRq : aSq;
    int rbase = routed ? g_offs[e] : 0;
    int mcount = routed ? (g_offs[e + 1] - rbase) : T;
    int m0 = blockIdx.x * 128;
    if (m0 >= mcount) return;
    int n0f = ytile * 64;
    int tid = threadIdx.x;

    if (tid < 128) {
        int r = m0 + tid; if (r > mcount - 1) r = mcount - 1;
        toks[tid] = routed ? g_bucket[rbase + r] : r;
    }
    __syncthreads();

    uint32_t sbase = cvta_s(sm);
    const int K = D_;
    const int nst = K / KSZ;            // 16

    auto load_stage = [&](int s) {
        uint32_t sb = sbase + (uint32_t)(s % NSTAGE) * STAGEB;
        int k0 = s * KSZ;
#pragma unroll
        for (int j = 0; j < 8; j++) {
            int c = tid + 256 * j;
            int mat = c >> 10;            // 0=A, 1=B
            int rc = c & 1023;
            int row = rc >> 3;
            int ch = rc & 7;
            uint32_t dst = sb + (uint32_t)(mat * MATB + (row * STR + ch * 8) * 2);
            const __half* src;
            if (mat == 0) {
                src = xq + (size_t)toks[row] * K + k0 + ch * 8;
            } else {
                int f = n0f + (row >> 1);
                int srow = (row & 1) ? (hid + f) : f;
                src = W + (size_t)srow * K + k0 + ch * 8;
            }
            CPA(dst, src);
        }
        CPC();
    };

    int wid = tid >> 5, lane = tid & 31;
    int wm = wid >> 2, wn = wid & 3;

    float c[4][4][4];
#pragma unroll
    for (int a = 0; a < 4; a++)
#pragma unroll
        for (int b = 0; b < 4; b++)
#pragma unroll
            for (int d = 0; d < 4; d++) c[a][b][d] = 0.f;

    int arow = wm * 64 + (lane & 15);
    int acol0 = (lane >> 4) * 8;
    int g8 = lane >> 3;
    int brin = lane & 7;

    uint32_t af[2][4][4], bf[2][4][2];
    auto ldfrags = [&](uint32_t Ab, uint32_t Bb, int ks, int buf) {
#pragma unroll
        for (int mi = 0; mi < 4; mi++) {
            uint32_t off = (uint32_t)((arow + mi * 16) * STR + ks * 16 + acol0) * 2;
            LDM4(af[buf][mi][0], af[buf][mi][1], af[buf][mi][2], af[buf][mi][3], Ab + off);
        }
#pragma unroll
        for (int j2 = 0; j2 < 2; j2++) {
            int nf = j2 * 2 + (g8 >> 1);
            uint32_t off = (uint32_t)((wn * 32 + nf * 8 + brin) * STR + ks * 16 + (g8 & 1) * 8) * 2;
            uint32_t r0, r1, r2, r3;
            LDM4(r0, r1, r2, r3, Bb + off);
            bf[buf][j2 * 2][0] = r0; bf[buf][j2 * 2][1] = r1;
            bf[buf][j2 * 2 + 1][0] = r2; bf[buf][j2 * 2 + 1][1] = r3;
        }
    };

    load_stage(0);
    load_stage(1);
    for (int s = 0; s < nst; s++) {
        if (s + 1 < nst) { CPW1(); } else { CPW0(); }
        __syncthreads();            // single barrier: orders prev-stage reads before load(s+2) writes
        uint32_t sb = sbase + (uint32_t)(s % NSTAGE) * STAGEB;
        uint32_t Ab = sb;
        uint32_t Bb = sb + MATB;
        ldfrags(Ab, Bb, 0, 0);
#pragma unroll
        for (int ks = 0; ks < 4; ks++) {
            int cur = ks & 1;
            if (ks < 3) ldfrags(Ab, Bb, ks + 1, cur ^ 1);
#pragma unroll
            for (int mi = 0; mi < 4; mi++)
#pragma unroll
                for (int nj = 0; nj < 4; nj++) MMA(c[mi][nj], af[cur][mi], bf[cur][nj]);
        }
        if (s + 2 < nst) load_stage(s + 2);
    }

    int rrem = mcount - m0;
#pragma unroll
    for (int mi = 0; mi < 4; mi++)
#pragma unroll
        for (int half = 0; half < 2; half++) {
            int row = wm * 64 + mi * 16 + (lane >> 2) + half * 8;
            if (row < rrem) {
                size_t rb = (size_t)(rbase + m0 + row) * hid;
#pragma unroll
                for (int nj = 0; nj < 4; nj++) {
                    float y = c[mi][nj][half * 2 + 0];
                    float g = c[mi][nj][half * 2 + 1];
                    float a = y * g / (1.f + __expf(-g));
                    int f = n0f + wn * 16 + nj * 4 + (lane & 3);
                    Oq[rb + f] = __float2half_rn(a);
                }
            }
        }
}

// ======================================================================
// fc2 merged (shared z=0 first, routed z=1..8): fp16 GEMM 128x128,
// K-stage 64, 3-stage pipeline + register double-buffered fragments.
// Output pre-zeroed; both paths atomicAdd.
// ======================================================================
__global__ __launch_bounds__(256, 2)
void k_fc2(const __half* __restrict__ aRq, const __half* __restrict__ aSq,
           const __half* __restrict__ W2q, const __half* __restrict__ S2q,
           float* __restrict__ out, int T) {
    extern __shared__ __half sm[];
    __shared__ int   toks[128];
    __shared__ int   etok[128];
    __shared__ float ew[128];

    int z = blockIdx.z;
    bool routed = z >= 1;
    int e = routed ? z - 1 : 0;
    int K = routed ? H_ : HS_;
    const __half* A = routed ? aRq : aSq;
    const __half* W = routed ? W2q + (size_t)e * D_ * H_ : S2q;
    int rbase = routed ? g_offs[e] : 0;
    int mcount = routed ? (g_offs[e + 1] - rbase) : T;
    int m0 = blockIdx.x * 128;
    if (m0 >= mcount) return;
    int n0 = blockIdx.y * 128;
    int tid = threadIdx.x;

    if (tid < 128) {
        int r = m0 + tid; if (r > mcount - 1) r = mcount - 1;
        toks[tid] = rbase + r;
        if (routed) { etok[tid] = g_bucket[rbase + r]; ew[tid] = g_bw[rbase + r]; }
        else        { etok[tid] = r;                   ew[tid] = 1.f; }
    }
    __syncthreads();

    uint32_t sbase = cvta_s(sm);
    const int nst = K / KSZ;            // 12 or 24

    auto load_stage = [&](int s) {
        uint32_t sb = sbase + (uint32_t)(s % NSTAGE) * STAGEB;
        int k0 = s * KSZ;
#pragma unroll
        for (int j = 0; j < 8; j++) {
            int c = tid + 256 * j;
            int mat = c >> 10;            // 0=A, 1=B
            int rc = c & 1023;
            int row = rc >> 3;
            int ch = rc & 7;
            uint32_t dst = sb + (uint32_t)(mat * MATB + (row * STR + ch * 8) * 2);
            const __half* src;
            if (mat == 0) {
                src = A + (size_t)toks[row] * K + k0 + ch * 8;
            } else {
                src = W + (size_t)(n0 + row) * K + k0 + ch * 8;
            }
            CPA(dst, src);
        }
        CPC();
    };

    int wid = tid >> 5, lane = tid & 31;
    int wm = wid >> 2, wn = wid & 3;

    float c[4][4][4];
#pragma unroll
    for (int a = 0; a < 4; a++)
#pragma unroll
        for (int b = 0; b < 4; b++)
#pragma unroll
            for (int d = 0; d < 4; d++) c[a][b][d] = 0.f;

    int arow = wm * 64 + (lane & 15);
    int acol0 = (lane >> 4) * 8;
    int g8 = lane >> 3;
    int brin = lane & 7;

    uint32_t af[2][4][4], bf[2][4][2];
    auto ldfrags = [&](uint32_t Ab, uint32_t Bb, int ks, int buf) {
#pragma unroll
        for (int mi = 0; mi < 4; mi++) {
            uint32_t off = (uint32_t)((arow + mi * 16) * STR + ks * 16 + acol0) * 2;
            LDM4(af[buf][mi][0], af[buf][mi][1], af[buf][mi][2], af[buf][mi][3], Ab + off);
        }
#pragma unroll
        for (int j2 = 0; j2 < 2; j2++) {
            int nf = j2 * 2 + (g8 >> 1);
            uint32_t off = (uint32_t)((wn * 32 + nf * 8 + brin) * STR + ks * 16 + (g8 & 1) * 8) * 2;
            uint32_t r0, r1, r2, r3;
            LDM4(r0, r1, r2, r3, Bb + off);
            bf[buf][j2 * 2][0] = r0; bf[buf][j2 * 2][1] = r1;
            bf[buf][j2 * 2 + 1][0] = r2; bf[buf][j2 * 2 + 1][1] = r3;
        }
    };

    load_stage(0);
    load_stage(1);
    for (int s = 0; s < nst; s++) {
        if (s + 1 < nst) { CPW1(); } else { CPW0(); }
        __syncthreads();
        uint32_t sb = sbase + (uint32_t)(s % NSTAGE) * STAGEB;
        uint32_t Ab = sb;
        uint32_t Bb = sb + MATB;
        ldfrags(Ab, Bb, 0, 0);
#pragma unroll
        for (int ks = 0; ks < 4; ks++) {
            int cur = ks & 1;
            if (ks < 3) ldfrags(Ab, Bb, ks + 1, cur ^ 1);
#pragma unroll
            for (int mi = 0; mi < 4; mi++)
#pragma unroll
                for (int nj = 0; nj < 4; nj++) MMA(c[mi][nj], af[cur][mi], bf[cur][nj]);
        }
        if (s + 2 < nst) load_stage(s + 2);
    }

    int rrem = mcount - m0;
#pragma unroll
    for (int mi = 0; mi < 4; mi++)
#pragma unroll
        for (int half = 0; half < 2; half++) {
            int row = wm * 64 + mi * 16 + (lane >> 2) + half * 8;
            if (row < rrem) {
                int t = etok[row]; float w = ew[row];
                float* base = out + (size_t)t * D_;
#pragma unroll
                for (int nj = 0; nj < 4; nj++) {
                    int col = n0 + wn * 32 + nj * 8 + (lane & 3) * 2;
                    atomicAdd(base + col,     w * c[mi][nj][half * 2 + 0]);
                    atomicAdd(base + col + 1, w * c[mi][nj][half * 2 + 1]);
                }
            }
        }
}

// ---------------- launcher ----------------
extern "C" void kernel_launch(void* const* d_in, const int* in_sizes, int n_in,
                              void* d_out, int out_size) {
    const float* x   = (const float*)d_in[0];
    const float* gw  = (const float*)d_in[1];
    const float* W1  = (const float*)d_in[2];
    const float* W2  = (const float*)d_in[3];
    const float* Ws1 = (const float*)d_in[4];
    const float* Ws2 = (const float*)d_in[5];
    float* out = (float*)d_out;

    int T = in_sizes[0] / D_;
    if (T > TMAX) T = TMAX;

    __half *xq, *W1q, *W2q, *S1q, *S2q, *aRq, *aSq;
    cudaGetSymbolAddress((void**)&xq,  g_xq);
    cudaGetSymbolAddress((void**)&W1q, g_W1q);
    cudaGetSymbolAddress((void**)&W2q, g_W2q);
    cudaGetSymbolAddress((void**)&S1q, g_S1q);
    cudaGetSymbolAddress((void**)&S2q, g_S2q);
    cudaGetSymbolAddress((void**)&aRq, g_aRq);
    cudaGetSymbolAddress((void**)&aSq, g_aSq);

    cudaFuncSetAttribute(k_fc1, cudaFuncAttributeMaxDynamicSharedMemorySize, SMEM_BYTES);
    cudaFuncSetAttribute(k_fc2, cudaFuncAttributeMaxDynamicSharedMemorySize, SMEM_BYTES);

    // fused conversion + counter zero + output zero (single launch)
    CvtArgs ca;
    ca.s[0] = x;   ca.h[0] = xq;
    ca.s[1] = W1;  ca.h[1] = W1q;
    ca.s[2] = W2;  ca.h[2] = W2q;
    ca.s[3] = Ws1; ca.h[3] = S1q;
    ca.s[4] = Ws2; ca.h[4] = S2q;
    ca.outz = out;
    int nb[6] = {
        (T * D_ / 8) / 256,
        (E_ * 2 * H_ * D_ / 8) / 256,
        (E_ * D_ * H_ / 8) / 256,
        (2 * HS_ * D_ / 8) / 256,
        (D_ * HS_ / 8) / 256,
        (T * D_ / 8) / 256            // output zeroing region
    };
    int cum = 0;
    for (int i = 0; i < 6; i++) { cum += nb[i]; ca.bend[i] = cum; }
    k_cvt_all<<<cum, 256>>>(ca);

    // routing: gate, then scatter (offsets fused into scatter)
    k_gate<<<(T + 7) / 8, 256>>>(x, gw, T);
    k_scatter<<<(T * 2 + 255) / 256, 256>>>(T);

    int mt = (T + 127) / 128;

    // fc1 merged: 24 shared tiles + 96 routed tiles in one launch
    k_fc1<<<dim3(mt, 120), 256, SMEM_BYTES>>>(xq, W1q, S1q, aRq, aSq, T);

    // fc2 merged: shared (z=0, scheduled first) + routed (z=1..8)
    k_fc2<<<dim3(mt, D_ / 128, 1 + E_), 256, SMEM_BYTES>>>(aRq, aSq, W2q, S2q, out, T);
}